// round 1
// baseline (speedup 1.0000x reference)
#include <cuda_runtime.h>
#include <cuda_bf16.h>
#include <math.h>

// Problem constants
#define BB 2
#define SS 2048
#define DD 1024
#define HH 16
#define DH 64
#define FF 4096
#define ROWS (BB*SS)          // 4096
#define WINDOW 128
#define NGLOB 16
#define NEGV -1e9f

// ---------------- scratch (device globals; no allocation allowed) ----------------
__device__ float g_hln[ROWS * DD];     // LN output (reused for LN1 and LN2)
__device__ float g_qkv[ROWS * 3 * DD]; // qkv projection
__device__ float g_o  [ROWS * DD];     // attention output
__device__ float g_x1 [ROWS * DD];     // x + attn residual
__device__ float g_h2 [ROWS * FF];     // gelu(mlp hidden)

// ---------------- LayerNorm ----------------
__global__ __launch_bounds__(256) void ln_kernel(const float* __restrict__ x,
                                                 const float* __restrict__ g,
                                                 const float* __restrict__ bt,
                                                 float* __restrict__ out)
{
    int row = blockIdx.x;
    const float* xr = x + (long)row * DD;
    float v[4];
    float s = 0.f, s2 = 0.f;
#pragma unroll
    for (int i = 0; i < 4; i++) {
        v[i] = xr[threadIdx.x + i * 256];
        s += v[i];
        s2 += v[i] * v[i];
    }
    int lane = threadIdx.x & 31, warp = threadIdx.x >> 5;
#pragma unroll
    for (int off = 16; off > 0; off >>= 1) {
        s  += __shfl_xor_sync(0xffffffffu, s,  off);
        s2 += __shfl_xor_sync(0xffffffffu, s2, off);
    }
    __shared__ float sm[8], sm2[8];
    if (lane == 0) { sm[warp] = s; sm2[warp] = s2; }
    __syncthreads();
    if (threadIdx.x == 0) {
        float a = 0.f, b = 0.f;
#pragma unroll
        for (int i = 0; i < 8; i++) { a += sm[i]; b += sm2[i]; }
        float mean = a * (1.0f / DD);
        float var  = b * (1.0f / DD) - mean * mean;
        sm[0] = mean;
        sm2[0] = rsqrtf(var + 1e-5f);
    }
    __syncthreads();
    float mean = sm[0], inv = sm2[0];
    float* orow = out + (long)row * DD;
#pragma unroll
    for (int i = 0; i < 4; i++) {
        int c = threadIdx.x + i * 256;
        orow[c] = (v[i] - mean) * inv * g[c] + bt[c];
    }
}

// ---------------- SGEMM: C[M,N] = A[M,K] @ W[N,K]^T + bias (+res) (+gelu) ----------------
#define BM 128
#define BN 128
#define BK 16

template <bool GELU, bool RES>
__global__ __launch_bounds__(256) void gemm_nt(const float* __restrict__ A,
                                               const float* __restrict__ W,
                                               const float* __restrict__ bias,
                                               const float* __restrict__ res,
                                               float* __restrict__ C,
                                               int M, int N, int K)
{
    __shared__ float As[BK][BM];
    __shared__ float Bs[BK][BN];

    int tid = threadIdx.x;
    int tx = tid & 15;        // 0..15  (col group)
    int ty = tid >> 4;        // 0..15  (row group)
    int m0 = blockIdx.y * BM;
    int n0 = blockIdx.x * BN;

    int lr = tid >> 2;               // 0..63
    int lc = (tid & 3) << 2;         // 0,4,8,12
    const float* Aptr = A + (long)(m0 + lr) * K + lc;
    const float* Wptr = W + (long)(n0 + lr) * K + lc;

    float acc[8][8];
#pragma unroll
    for (int i = 0; i < 8; i++)
#pragma unroll
        for (int j = 0; j < 8; j++) acc[i][j] = 0.f;

    for (int k0 = 0; k0 < K; k0 += BK) {
        float4 a0 = *(const float4*)(Aptr + k0);
        float4 a1 = *(const float4*)(Aptr + (long)64 * K + k0);
        float4 b0 = *(const float4*)(Wptr + k0);
        float4 b1 = *(const float4*)(Wptr + (long)64 * K + k0);
        __syncthreads();
        As[lc + 0][lr] = a0.x; As[lc + 1][lr] = a0.y; As[lc + 2][lr] = a0.z; As[lc + 3][lr] = a0.w;
        As[lc + 0][lr + 64] = a1.x; As[lc + 1][lr + 64] = a1.y; As[lc + 2][lr + 64] = a1.z; As[lc + 3][lr + 64] = a1.w;
        Bs[lc + 0][lr] = b0.x; Bs[lc + 1][lr] = b0.y; Bs[lc + 2][lr] = b0.z; Bs[lc + 3][lr] = b0.w;
        Bs[lc + 0][lr + 64] = b1.x; Bs[lc + 1][lr + 64] = b1.y; Bs[lc + 2][lr + 64] = b1.z; Bs[lc + 3][lr + 64] = b1.w;
        __syncthreads();
#pragma unroll
        for (int kk = 0; kk < BK; kk++) {
            float ra[8], rb[8];
            *(float4*)(ra)     = *(const float4*)&As[kk][ty * 4];
            *(float4*)(ra + 4) = *(const float4*)&As[kk][64 + ty * 4];
            *(float4*)(rb)     = *(const float4*)&Bs[kk][tx * 4];
            *(float4*)(rb + 4) = *(const float4*)&Bs[kk][64 + tx * 4];
#pragma unroll
            for (int i = 0; i < 8; i++)
#pragma unroll
                for (int j = 0; j < 8; j++)
                    acc[i][j] = fmaf(ra[i], rb[j], acc[i][j]);
        }
    }

#pragma unroll
    for (int i = 0; i < 8; i++) {
        int m = m0 + ((i < 4) ? (ty * 4 + i) : (64 + ty * 4 + i - 4));
#pragma unroll
        for (int j = 0; j < 8; j++) {
            int n = n0 + ((j < 4) ? (tx * 4 + j) : (64 + tx * 4 + j - 4));
            float v = acc[i][j] + bias[n];
            if (RES) v += res[(long)m * N + n];
            if (GELU) v = 0.5f * v * (1.0f + erff(v * 0.70710678118654752f));
            C[(long)m * N + n] = v;
        }
    }
}

// ---------------- Sparse attention: one warp per (b, h, query) ----------------
// keys: j in [0, min(i+1,16)) union [max(16, i-128), i]   (causal, window 128, 16 globals)
__global__ __launch_bounds__(256) void attn_kernel(const float* __restrict__ qkv,
                                                   const int* __restrict__ am,
                                                   float* __restrict__ o)
{
    __shared__ float sc[8][160];
    int warp = threadIdx.x >> 5, lane = threadIdx.x & 31;
    long gw = (long)blockIdx.x * 8 + warp;       // 0 .. B*H*S-1
    int s = (int)(gw % SS);
    int h = (int)((gw / SS) % HH);
    int b = (int)(gw / ((long)SS * HH));

    const float* qp = qkv + ((long)(b * SS + s)) * (3 * DD) + h * DH + lane * 2;
    float2 q = *(const float2*)qp;

    int gend = min(s + 1, NGLOB);                 // global keys [0, gend)
    int wstart = max(NGLOB, s - WINDOW);          // window keys [wstart, s]
    int nwin = (s >= NGLOB) ? (s - wstart + 1) : 0;
    int nk = gend + nwin;

    float mx = -1e30f;
    for (int idx = 0; idx < nk; idx++) {
        int j = (idx < gend) ? idx : (wstart + (idx - gend));
        const float* kp = qkv + ((long)(b * SS + j)) * (3 * DD) + DD + h * DH + lane * 2;
        float2 k2 = *(const float2*)kp;
        float p = q.x * k2.x + q.y * k2.y;
        p += __shfl_xor_sync(0xffffffffu, p, 16);
        p += __shfl_xor_sync(0xffffffffu, p, 8);
        p += __shfl_xor_sync(0xffffffffu, p, 4);
        p += __shfl_xor_sync(0xffffffffu, p, 2);
        p += __shfl_xor_sync(0xffffffffu, p, 1);
        p *= 0.125f;                               // 1/sqrt(64)
        if (am[b * SS + j] == 0) p = NEGV;
        if (lane == 0) sc[warp][idx] = p;
        mx = fmaxf(mx, p);
    }
    __syncwarp();

    float denom = 0.f;
    float2 acc = make_float2(0.f, 0.f);
    for (int idx = 0; idx < nk; idx++) {
        int j = (idx < gend) ? idx : (wstart + (idx - gend));
        float pv = __expf(sc[warp][idx] - mx);
        const float* vp = qkv + ((long)(b * SS + j)) * (3 * DD) + 2 * DD + h * DH + lane * 2;
        float2 v2 = *(const float2*)vp;
        acc.x = fmaf(pv, v2.x, acc.x);
        acc.y = fmaf(pv, v2.y, acc.y);
        denom += pv;
    }
    float inv = 1.f / denom;
    float* op = o + ((long)(b * SS + s)) * DD + h * DH + lane * 2;
    op[0] = acc.x * inv;
    op[1] = acc.y * inv;
}

// ---------------- launch ----------------
extern "C" void kernel_launch(void* const* d_in, const int* in_sizes, int n_in,
                              void* d_out, int out_size)
{
    const float* x     = (const float*)d_in[0];
    const int*   am    = (const int*)  d_in[1];
    const float* w_in  = (const float*)d_in[2];
    const float* b_in  = (const float*)d_in[3];
    const float* w_out = (const float*)d_in[4];
    const float* b_out = (const float*)d_in[5];
    const float* g1    = (const float*)d_in[6];
    const float* bl1   = (const float*)d_in[7];
    const float* g2    = (const float*)d_in[8];
    const float* bl2   = (const float*)d_in[9];
    const float* w1    = (const float*)d_in[10];
    const float* b1    = (const float*)d_in[11];
    const float* w2    = (const float*)d_in[12];
    const float* b2    = (const float*)d_in[13];
    float* out = (float*)d_out;

    void *p_hln, *p_qkv, *p_o, *p_x1, *p_h2;
    cudaGetSymbolAddress(&p_hln, g_hln);
    cudaGetSymbolAddress(&p_qkv, g_qkv);
    cudaGetSymbolAddress(&p_o,   g_o);
    cudaGetSymbolAddress(&p_x1,  g_x1);
    cudaGetSymbolAddress(&p_h2,  g_h2);
    float* hln = (float*)p_hln;
    float* qkv = (float*)p_qkv;
    float* o   = (float*)p_o;
    float* x1  = (float*)p_x1;
    float* h2  = (float*)p_h2;

    // 1. LN1
    ln_kernel<<<ROWS, 256>>>(x, g1, bl1, hln);
    // 2. qkv = hln @ w_in^T + b_in      [4096 x 3072]
    gemm_nt<false, false><<<dim3(3 * DD / BN, ROWS / BM), 256>>>(hln, w_in, b_in, nullptr, qkv, ROWS, 3 * DD, DD);
    // 3. attention -> o
    attn_kernel<<<(BB * HH * SS) / 8, 256>>>(qkv, am, o);
    // 4. x1 = x + o @ w_out^T + b_out   [4096 x 1024]
    gemm_nt<false, true><<<dim3(DD / BN, ROWS / BM), 256>>>(o, w_out, b_out, x, x1, ROWS, DD, DD);
    // 5. LN2
    ln_kernel<<<ROWS, 256>>>(x1, g2, bl2, hln);
    // 6. h2 = gelu(hln @ w1^T + b1)     [4096 x 4096]
    gemm_nt<true, false><<<dim3(FF / BN, ROWS / BM), 256>>>(hln, w1, b1, nullptr, h2, ROWS, FF, DD);
    // 7. out = x1 + h2 @ w2^T + b2      [4096 x 1024]
    gemm_nt<false, true><<<dim3(DD / BN, ROWS / BM), 256>>>(h2, w2, b2, x1, out, ROWS, DD, FF);
}

// round 3
// speedup vs baseline: 1.9541x; 1.9541x over previous
#include <cuda_runtime.h>
#include <math.h>
#include <cstdint>

// Problem constants
#define BB 2
#define SS 2048
#define DD 1024
#define HH 16
#define DH 64
#define FF 4096
#define ROWS (BB*SS)          // 4096
#define WINDOW 128
#define NGLOB 16
#define NEGV -1e9f

// ---------------- scratch (device globals; no allocation allowed) ----------------
__device__ float g_hln[ROWS * DD];     // LN output (reused for LN1 and LN2)
__device__ float g_qkv[ROWS * 3 * DD]; // qkv projection
__device__ float g_o  [ROWS * DD];     // attention output
__device__ float g_x1 [ROWS * DD];     // x + attn residual
__device__ float g_h2 [ROWS * FF];     // gelu(mlp hidden)

// ---------------- helpers ----------------
__device__ __forceinline__ uint32_t tf32r(float f) {
    uint32_t u;
    asm("cvt.rna.tf32.f32 %0, %1;" : "=r"(u) : "f"(f));
    return u;
}

#define MMA_TF32(c, a, b) \
    asm volatile("mma.sync.aligned.m16n8k8.row.col.f32.tf32.tf32.f32 " \
        "{%0,%1,%2,%3}, {%4,%5,%6,%7}, {%8,%9}, {%0,%1,%2,%3};" \
        : "+f"((c)[0]), "+f"((c)[1]), "+f"((c)[2]), "+f"((c)[3]) \
        : "r"((a)[0]), "r"((a)[1]), "r"((a)[2]), "r"((a)[3]), \
          "r"((b)[0]), "r"((b)[1]))

// ---------------- tf32 mma.sync GEMM: C[M,N] = A[M,K] @ W[N,K]^T + bias (+res)(+gelu)
// CTA tile 128x128, BK=16, 8 warps (2 M x 4 N), warp tile 64x32.
#define LDS_STRIDE 20          // conflict-free: (20*r + c) % 32 covers all banks

template <bool GELU, bool RES>
__global__ __launch_bounds__(256, 2) void gemm_mma(const float* __restrict__ A,
                                                   const float* __restrict__ W,
                                                   const float* __restrict__ bias,
                                                   const float* __restrict__ res,
                                                   float* __restrict__ C,
                                                   int M, int N, int K)
{
    __shared__ float As[2][128 * LDS_STRIDE];
    __shared__ float Bs[2][128 * LDS_STRIDE];

    int tid = threadIdx.x;
    int lane = tid & 31, wid = tid >> 5;
    int m0 = blockIdx.y * 128;
    int n0 = blockIdx.x * 128;
    int wm = (wid & 1) * 64;          // warp M offset
    int wn = (wid >> 1) * 32;         // warp N offset

    // global load mapping: each thread loads 2 float4 from A and 2 from B per stage
    int lrow = tid >> 2;              // 0..63
    int lcol = (tid & 3) * 4;         // 0,4,8,12
    const float* Ag = A + (long)(m0 + lrow) * K + lcol;
    const float* Bg = W + (long)(n0 + lrow) * K + lcol;

    float acc[4][4][4];
#pragma unroll
    for (int i = 0; i < 4; i++)
#pragma unroll
        for (int j = 0; j < 4; j++)
#pragma unroll
            for (int c = 0; c < 4; c++) acc[i][j][c] = 0.f;

    int nIter = K >> 4;

    float4 ra[2], rb[2];
    // preload stage 0
    ra[0] = *(const float4*)(Ag);
    ra[1] = *(const float4*)(Ag + (long)64 * K);
    rb[0] = *(const float4*)(Bg);
    rb[1] = *(const float4*)(Bg + (long)64 * K);
#pragma unroll
    for (int i = 0; i < 2; i++) {
        float4 v = ra[i];
        *(float4*)&As[0][(lrow + 64 * i) * LDS_STRIDE + lcol] =
            make_float4(__uint_as_float(tf32r(v.x)), __uint_as_float(tf32r(v.y)),
                        __uint_as_float(tf32r(v.z)), __uint_as_float(tf32r(v.w)));
        v = rb[i];
        *(float4*)&Bs[0][(lrow + 64 * i) * LDS_STRIDE + lcol] =
            make_float4(__uint_as_float(tf32r(v.x)), __uint_as_float(tf32r(v.y)),
                        __uint_as_float(tf32r(v.z)), __uint_as_float(tf32r(v.w)));
    }
    __syncthreads();

    for (int it = 0; it < nIter; it++) {
        int buf = it & 1;
        // issue next-stage global loads early (latency hidden under compute)
        if (it + 1 < nIter) {
            long k0 = (long)(it + 1) << 4;
            ra[0] = *(const float4*)(Ag + k0);
            ra[1] = *(const float4*)(Ag + (long)64 * K + k0);
            rb[0] = *(const float4*)(Bg + k0);
            rb[1] = *(const float4*)(Bg + (long)64 * K + k0);
        }

        // compute on current buffer: 2 k-steps of 8
        const float* Ab = As[buf];
        const float* Bb = Bs[buf];
#pragma unroll
        for (int ks = 0; ks < 2; ks++) {
            int c = ks * 8 + (lane & 3);
            uint32_t af[4][4], bf[4][2];
#pragma unroll
            for (int mi = 0; mi < 4; mi++) {
                int r = wm + mi * 16 + (lane >> 2);
                af[mi][0] = __float_as_uint(Ab[r * LDS_STRIDE + c]);
                af[mi][1] = __float_as_uint(Ab[(r + 8) * LDS_STRIDE + c]);
                af[mi][2] = __float_as_uint(Ab[r * LDS_STRIDE + c + 4]);
                af[mi][3] = __float_as_uint(Ab[(r + 8) * LDS_STRIDE + c + 4]);
            }
#pragma unroll
            for (int ni = 0; ni < 4; ni++) {
                int n = wn + ni * 8 + (lane >> 2);
                bf[ni][0] = __float_as_uint(Bb[n * LDS_STRIDE + c]);
                bf[ni][1] = __float_as_uint(Bb[n * LDS_STRIDE + c + 4]);
            }
#pragma unroll
            for (int mi = 0; mi < 4; mi++)
#pragma unroll
                for (int ni = 0; ni < 4; ni++)
                    MMA_TF32(acc[mi][ni], af[mi], bf[ni]);
        }

        // stage next buffer
        if (it + 1 < nIter) {
            int nb = buf ^ 1;
#pragma unroll
            for (int i = 0; i < 2; i++) {
                float4 v = ra[i];
                *(float4*)&As[nb][(lrow + 64 * i) * LDS_STRIDE + lcol] =
                    make_float4(__uint_as_float(tf32r(v.x)), __uint_as_float(tf32r(v.y)),
                                __uint_as_float(tf32r(v.z)), __uint_as_float(tf32r(v.w)));
                v = rb[i];
                *(float4*)&Bs[nb][(lrow + 64 * i) * LDS_STRIDE + lcol] =
                    make_float4(__uint_as_float(tf32r(v.x)), __uint_as_float(tf32r(v.y)),
                                __uint_as_float(tf32r(v.z)), __uint_as_float(tf32r(v.w)));
            }
            __syncthreads();
        }
    }

    // epilogue: acc[mi][ni] -> rows (lane>>2, +8), cols 2*(lane&3), +1
#pragma unroll
    for (int mi = 0; mi < 4; mi++) {
        long r_lo = m0 + wm + mi * 16 + (lane >> 2);
        long r_hi = r_lo + 8;
#pragma unroll
        for (int ni = 0; ni < 4; ni++) {
            int col = n0 + wn + ni * 8 + (lane & 3) * 2;
            float2 bv = *(const float2*)(bias + col);
            float v0 = acc[mi][ni][0] + bv.x;
            float v1 = acc[mi][ni][1] + bv.y;
            float v2 = acc[mi][ni][2] + bv.x;
            float v3 = acc[mi][ni][3] + bv.y;
            if (RES) {
                float2 r0 = *(const float2*)(res + r_lo * N + col);
                float2 r1 = *(const float2*)(res + r_hi * N + col);
                v0 += r0.x; v1 += r0.y; v2 += r1.x; v3 += r1.y;
            }
            if (GELU) {
                v0 = 0.5f * v0 * (1.0f + erff(v0 * 0.70710678118654752f));
                v1 = 0.5f * v1 * (1.0f + erff(v1 * 0.70710678118654752f));
                v2 = 0.5f * v2 * (1.0f + erff(v2 * 0.70710678118654752f));
                v3 = 0.5f * v3 * (1.0f + erff(v3 * 0.70710678118654752f));
            }
            *(float2*)(C + r_lo * N + col) = make_float2(v0, v1);
            *(float2*)(C + r_hi * N + col) = make_float2(v2, v3);
        }
    }
}

// ---------------- LayerNorm ----------------
__global__ __launch_bounds__(256) void ln_kernel(const float* __restrict__ x,
                                                 const float* __restrict__ g,
                                                 const float* __restrict__ bt,
                                                 float* __restrict__ out)
{
    int row = blockIdx.x;
    const float* xr = x + (long)row * DD;
    float v[4];
    float s = 0.f, s2 = 0.f;
#pragma unroll
    for (int i = 0; i < 4; i++) {
        v[i] = xr[threadIdx.x + i * 256];
        s += v[i];
        s2 += v[i] * v[i];
    }
    int lane = threadIdx.x & 31, warp = threadIdx.x >> 5;
#pragma unroll
    for (int off = 16; off > 0; off >>= 1) {
        s  += __shfl_xor_sync(0xffffffffu, s,  off);
        s2 += __shfl_xor_sync(0xffffffffu, s2, off);
    }
    __shared__ float sm[8], sm2[8];
    if (lane == 0) { sm[warp] = s; sm2[warp] = s2; }
    __syncthreads();
    if (threadIdx.x == 0) {
        float a = 0.f, b = 0.f;
#pragma unroll
        for (int i = 0; i < 8; i++) { a += sm[i]; b += sm2[i]; }
        float mean = a * (1.0f / DD);
        float var  = b * (1.0f / DD) - mean * mean;
        sm[0] = mean;
        sm2[0] = rsqrtf(var + 1e-5f);
    }
    __syncthreads();
    float mean = sm[0], inv = sm2[0];
    float* orow = out + (long)row * DD;
#pragma unroll
    for (int i = 0; i < 4; i++) {
        int c = threadIdx.x + i * 256;
        orow[c] = (v[i] - mean) * inv * g[c] + bt[c];
    }
}

// ---------------- Sparse attention: one warp per (b, h, query) ----------------
__global__ __launch_bounds__(256) void attn_kernel(const float* __restrict__ qkv,
                                                   const int* __restrict__ am,
                                                   float* __restrict__ o)
{
    __shared__ float sc[8][160];
    int warp = threadIdx.x >> 5, lane = threadIdx.x & 31;
    long gw = (long)blockIdx.x * 8 + warp;
    int s = (int)(gw % SS);
    int h = (int)((gw / SS) % HH);
    int b = (int)(gw / ((long)SS * HH));

    const float* qp = qkv + ((long)(b * SS + s)) * (3 * DD) + h * DH + lane * 2;
    float2 q = *(const float2*)qp;

    int gend = min(s + 1, NGLOB);
    int wstart = max(NGLOB, s - WINDOW);
    int nwin = (s >= NGLOB) ? (s - wstart + 1) : 0;
    int nk = gend + nwin;

    float mx = -1e30f;
    for (int idx = 0; idx < nk; idx++) {
        int j = (idx < gend) ? idx : (wstart + (idx - gend));
        const float* kp = qkv + ((long)(b * SS + j)) * (3 * DD) + DD + h * DH + lane * 2;
        float2 k2 = *(const float2*)kp;
        float p = q.x * k2.x + q.y * k2.y;
        p += __shfl_xor_sync(0xffffffffu, p, 16);
        p += __shfl_xor_sync(0xffffffffu, p, 8);
        p += __shfl_xor_sync(0xffffffffu, p, 4);
        p += __shfl_xor_sync(0xffffffffu, p, 2);
        p += __shfl_xor_sync(0xffffffffu, p, 1);
        p *= 0.125f;
        if (am[b * SS + j] == 0) p = NEGV;
        if (lane == 0) sc[warp][idx] = p;
        mx = fmaxf(mx, p);
    }
    __syncwarp();

    float denom = 0.f;
    float2 acc = make_float2(0.f, 0.f);
    for (int idx = 0; idx < nk; idx++) {
        int j = (idx < gend) ? idx : (wstart + (idx - gend));
        float pv = __expf(sc[warp][idx] - mx);
        const float* vp = qkv + ((long)(b * SS + j)) * (3 * DD) + 2 * DD + h * DH + lane * 2;
        float2 v2 = *(const float2*)vp;
        acc.x = fmaf(pv, v2.x, acc.x);
        acc.y = fmaf(pv, v2.y, acc.y);
        denom += pv;
    }
    float inv = 1.f / denom;
    float* op = o + ((long)(b * SS + s)) * DD + h * DH + lane * 2;
    op[0] = acc.x * inv;
    op[1] = acc.y * inv;
}

// ---------------- launch ----------------
extern "C" void kernel_launch(void* const* d_in, const int* in_sizes, int n_in,
                              void* d_out, int out_size)
{
    const float* x     = (const float*)d_in[0];
    const int*   am    = (const int*)  d_in[1];
    const float* w_in  = (const float*)d_in[2];
    const float* b_in  = (const float*)d_in[3];
    const float* w_out = (const float*)d_in[4];
    const float* b_out = (const float*)d_in[5];
    const float* g1    = (const float*)d_in[6];
    const float* bl1   = (const float*)d_in[7];
    const float* g2    = (const float*)d_in[8];
    const float* bl2   = (const float*)d_in[9];
    const float* w1    = (const float*)d_in[10];
    const float* b1    = (const float*)d_in[11];
    const float* w2    = (const float*)d_in[12];
    const float* b2    = (const float*)d_in[13];
    float* out = (float*)d_out;

    void *p_hln, *p_qkv, *p_o, *p_x1, *p_h2;
    cudaGetSymbolAddress(&p_hln, g_hln);
    cudaGetSymbolAddress(&p_qkv, g_qkv);
    cudaGetSymbolAddress(&p_o,   g_o);
    cudaGetSymbolAddress(&p_x1,  g_x1);
    cudaGetSymbolAddress(&p_h2,  g_h2);
    float* hln = (float*)p_hln;
    float* qkv = (float*)p_qkv;
    float* o   = (float*)p_o;
    float* x1  = (float*)p_x1;
    float* h2  = (float*)p_h2;

    // 1. LN1
    ln_kernel<<<ROWS, 256>>>(x, g1, bl1, hln);
    // 2. qkv = hln @ w_in^T + b_in      [4096 x 3072]
    gemm_mma<false, false><<<dim3(3 * DD / 128, ROWS / 128), 256>>>(hln, w_in, b_in, nullptr, qkv, ROWS, 3 * DD, DD);
    // 3. attention -> o
    attn_kernel<<<(BB * HH * SS) / 8, 256>>>(qkv, am, o);
    // 4. x1 = x + o @ w_out^T + b_out   [4096 x 1024]
    gemm_mma<false, true><<<dim3(DD / 128, ROWS / 128), 256>>>(o, w_out, b_out, x, x1, ROWS, DD, DD);
    // 5. LN2
    ln_kernel<<<ROWS, 256>>>(x1, g2, bl2, hln);
    // 6. h2 = gelu(hln @ w1^T + b1)     [4096 x 4096]
    gemm_mma<true, false><<<dim3(FF / 128, ROWS / 128), 256>>>(hln, w1, b1, nullptr, h2, ROWS, FF, DD);
    // 7. out = x1 + h2 @ w2^T + b2      [4096 x 1024]
    gemm_mma<false, true><<<dim3(DD / 128, ROWS / 128), 256>>>(h2, w2, b2, x1, out, ROWS, DD, FF);
}

// round 4
// speedup vs baseline: 2.4927x; 1.2756x over previous
#include <cuda_runtime.h>
#include <math.h>
#include <cstdint>

// Problem constants
#define BB 2
#define SS 2048
#define DD 1024
#define HH 16
#define DH 64
#define FF 4096
#define ROWS (BB*SS)          // 4096
#define WINDOW 128
#define NGLOB 16
#define NEGV -1e9f

// weight offsets inside g_wr
#define OFF_WIN  0
#define OFF_WOUT (3*DD*DD)                 // 3145728
#define OFF_W1   (OFF_WOUT + DD*DD)        // 4194304
#define OFF_W2   (OFF_W1 + FF*DD)          // 8388608
#define WTOTAL   (OFF_W2 + DD*FF)          // 12582912

// ---------------- scratch (device globals; no allocation allowed) ----------------
__device__ float g_hln[ROWS * DD];
__device__ float g_qkv[ROWS * 3 * DD];
__device__ float g_o  [ROWS * DD];
__device__ float g_x1 [ROWS * DD];
__device__ float g_h2 [ROWS * FF];
__device__ float g_wr [WTOTAL];            // tf32-rounded weights

// ---------------- helpers ----------------
__device__ __forceinline__ float tf32rf(float f) {
    uint32_t u;
    asm("cvt.rna.tf32.f32 %0, %1;" : "=r"(u) : "f"(f));
    return __uint_as_float(u);
}
__device__ __forceinline__ uint32_t smem_u32(const void* p) {
    uint32_t a;
    asm("{ .reg .u64 t; cvta.to.shared.u64 t, %1; cvt.u32.u64 %0, t; }" : "=r"(a) : "l"(p));
    return a;
}
#define CP_ASYNC16(sdst, gsrc) \
    asm volatile("cp.async.cg.shared.global [%0], [%1], 16;" :: "r"(sdst), "l"(gsrc))
#define CP_COMMIT() asm volatile("cp.async.commit_group;" ::: "memory")
#define CP_WAIT2()  asm volatile("cp.async.wait_group 2;" ::: "memory")

#define LDSM_X4(r0, r1, r2, r3, addr) \
    asm volatile("ldmatrix.sync.aligned.m8n8.x4.shared.b16 {%0,%1,%2,%3}, [%4];" \
        : "=r"(r0), "=r"(r1), "=r"(r2), "=r"(r3) : "r"(addr))

#define MMA_TF32(c, a, b) \
    asm volatile("mma.sync.aligned.m16n8k8.row.col.f32.tf32.tf32.f32 " \
        "{%0,%1,%2,%3}, {%4,%5,%6,%7}, {%8,%9}, {%0,%1,%2,%3};" \
        : "+f"((c)[0]), "+f"((c)[1]), "+f"((c)[2]), "+f"((c)[3]) \
        : "r"((a)[0]), "r"((a)[1]), "r"((a)[2]), "r"((a)[3]), \
          "r"((b)[0]), "r"((b)[1]))

// ---------------- weight tf32 pre-round ----------------
__global__ __launch_bounds__(256) void wprep_kernel(const float* __restrict__ w_in,
                                                    const float* __restrict__ w_out,
                                                    const float* __restrict__ w1,
                                                    const float* __restrict__ w2)
{
    long i = ((long)blockIdx.x * 256 + threadIdx.x) * 4;
    float4 v;
    if (i < OFF_WOUT) {
        v = *(const float4*)(w_in + i);
    } else if (i < OFF_W1) {
        v = *(const float4*)(w_out + (i - OFF_WOUT));
    } else if (i < OFF_W2) {
        v = *(const float4*)(w1 + (i - OFF_W1));
    } else {
        v = *(const float4*)(w2 + (i - OFF_W2));
    }
    v.x = tf32rf(v.x); v.y = tf32rf(v.y); v.z = tf32rf(v.z); v.w = tf32rf(v.w);
    *(float4*)(g_wr + i) = v;
}

// ---------------- tf32 mma.sync GEMM (cp.async 4-stage, ldmatrix fragments)
// C[M,N] = A[M,K] @ W[N,K]^T + bias (+res)(+gelu)(+tf32-round-out)
// CTA tile 128x128, BK=16, 8 warps (2M x 4N), warp tile 64x32.
// Inputs A and W MUST already be tf32-rounded.
#define ASTRIDE_B 80                // bytes per smem row (20 floats)
#define STAGE_BYTES 10240           // 128 rows * 80 B
#define NSTAGES 4
#define GEMM_SMEM (2 * NSTAGES * STAGE_BYTES)   // 81920

template <bool GELU, bool RES, bool RTF>
__global__ __launch_bounds__(256, 2) void gemm_mma(const float* __restrict__ A,
                                                   const float* __restrict__ W,
                                                   const float* __restrict__ bias,
                                                   const float* __restrict__ res,
                                                   float* __restrict__ C,
                                                   int M, int N, int K)
{
    extern __shared__ char smem[];
    uint32_t sA = smem_u32(smem);                       // A stages
    uint32_t sB = sA + NSTAGES * STAGE_BYTES;           // B stages

    int tid = threadIdx.x;
    int lane = tid & 31, wid = tid >> 5;
    int m0 = blockIdx.y * 128;
    int n0 = blockIdx.x * 128;
    int wm = (wid & 1) * 64;
    int wn = (wid >> 1) * 32;

    // cp.async mapping: 2 chunks of A + 2 of B per thread per stage
    int ldr0 = tid >> 2;             // 0..63
    int ldr1 = ldr0 + 64;            // 64..127
    int ldc  = (tid & 3) * 16;       // byte offset within row (0,16,32,48)
    const float* Ag0 = A + (long)(m0 + ldr0) * K + (tid & 3) * 4;
    const float* Ag1 = A + (long)(m0 + ldr1) * K + (tid & 3) * 4;
    const float* Bg0 = W + (long)(n0 + ldr0) * K + (tid & 3) * 4;
    const float* Bg1 = W + (long)(n0 + ldr1) * K + (tid & 3) * 4;
    uint32_t sa0 = sA + ldr0 * ASTRIDE_B + ldc;
    uint32_t sa1 = sA + ldr1 * ASTRIDE_B + ldc;
    uint32_t sb0 = sB + ldr0 * ASTRIDE_B + ldc;
    uint32_t sb1 = sB + ldr1 * ASTRIDE_B + ldc;

    // ldmatrix per-thread offsets
    int g = lane >> 3;               // 0..3
    int rl = lane & 7;
    // A: matrices [rows0-7@c0, rows8-15@c0, rows0-7@c16B, rows8-15@c16B]
    uint32_t aoff = (uint32_t)(((g & 1) * 8 + rl) * ASTRIDE_B + (g >> 1) * 16) + (wm * ASTRIDE_B);
    // B: matrices [n0-7@k0, n0-7@k16B, n8-15@k0, n8-15@k16B]
    uint32_t boff = (uint32_t)(((g >> 1) * 8 + rl) * ASTRIDE_B + (g & 1) * 16) + (wn * ASTRIDE_B);

    float acc[4][4][4];
#pragma unroll
    for (int i = 0; i < 4; i++)
#pragma unroll
        for (int j = 0; j < 4; j++)
#pragma unroll
            for (int c = 0; c < 4; c++) acc[i][j][c] = 0.f;

    int nIter = K >> 4;

    // prologue: stages 0..2
#pragma unroll
    for (int s = 0; s < NSTAGES - 1; s++) {
        long k0 = (long)s << 4;
        uint32_t so = s * STAGE_BYTES;
        CP_ASYNC16(sa0 + so, Ag0 + k0);
        CP_ASYNC16(sa1 + so, Ag1 + k0);
        CP_ASYNC16(sb0 + so, Bg0 + k0);
        CP_ASYNC16(sb1 + so, Bg1 + k0);
        CP_COMMIT();
    }

    for (int it = 0; it < nIter; it++) {
        CP_WAIT2();
        __syncthreads();

        // issue stage it+3
        if (it + NSTAGES - 1 < nIter) {
            long k0 = (long)(it + NSTAGES - 1) << 4;
            uint32_t so = ((it + NSTAGES - 1) & (NSTAGES - 1)) * STAGE_BYTES;
            CP_ASYNC16(sa0 + so, Ag0 + k0);
            CP_ASYNC16(sa1 + so, Ag1 + k0);
            CP_ASYNC16(sb0 + so, Bg0 + k0);
            CP_ASYNC16(sb1 + so, Bg1 + k0);
        }
        CP_COMMIT();

        uint32_t slot = (it & (NSTAGES - 1)) * STAGE_BYTES;
        uint32_t abase = sA + slot + aoff;
        uint32_t bbase = sB + slot + boff;
#pragma unroll
        for (int ks = 0; ks < 2; ks++) {
            uint32_t af[4][4], bf[4][2];
#pragma unroll
            for (int mi = 0; mi < 4; mi++)
                LDSM_X4(af[mi][0], af[mi][1], af[mi][2], af[mi][3],
                        abase + mi * (16 * ASTRIDE_B) + ks * 32);
#pragma unroll
            for (int p = 0; p < 2; p++)
                LDSM_X4(bf[2*p][0], bf[2*p][1], bf[2*p+1][0], bf[2*p+1][1],
                        bbase + p * (16 * ASTRIDE_B) + ks * 32);
#pragma unroll
            for (int mi = 0; mi < 4; mi++)
#pragma unroll
                for (int ni = 0; ni < 4; ni++)
                    MMA_TF32(acc[mi][ni], af[mi], bf[ni]);
        }
        __syncthreads();
    }

    // epilogue
#pragma unroll
    for (int mi = 0; mi < 4; mi++) {
        long r_lo = m0 + wm + mi * 16 + (lane >> 2);
        long r_hi = r_lo + 8;
#pragma unroll
        for (int ni = 0; ni < 4; ni++) {
            int col = n0 + wn + ni * 8 + (lane & 3) * 2;
            float2 bv = *(const float2*)(bias + col);
            float v0 = acc[mi][ni][0] + bv.x;
            float v1 = acc[mi][ni][1] + bv.y;
            float v2 = acc[mi][ni][2] + bv.x;
            float v3 = acc[mi][ni][3] + bv.y;
            if (RES) {
                float2 r0 = *(const float2*)(res + r_lo * N + col);
                float2 r1 = *(const float2*)(res + r_hi * N + col);
                v0 += r0.x; v1 += r0.y; v2 += r1.x; v3 += r1.y;
            }
            if (GELU) {
                v0 = 0.5f * v0 * (1.0f + erff(v0 * 0.70710678118654752f));
                v1 = 0.5f * v1 * (1.0f + erff(v1 * 0.70710678118654752f));
                v2 = 0.5f * v2 * (1.0f + erff(v2 * 0.70710678118654752f));
                v3 = 0.5f * v3 * (1.0f + erff(v3 * 0.70710678118654752f));
            }
            if (RTF) {
                v0 = tf32rf(v0); v1 = tf32rf(v1); v2 = tf32rf(v2); v3 = tf32rf(v3);
            }
            *(float2*)(C + r_lo * N + col) = make_float2(v0, v1);
            *(float2*)(C + r_hi * N + col) = make_float2(v2, v3);
        }
    }
}

// ---------------- LayerNorm (outputs tf32-rounded) ----------------
__global__ __launch_bounds__(256) void ln_kernel(const float* __restrict__ x,
                                                 const float* __restrict__ g,
                                                 const float* __restrict__ bt,
                                                 float* __restrict__ out)
{
    int row = blockIdx.x;
    const float* xr = x + (long)row * DD;
    float v[4];
    float s = 0.f, s2 = 0.f;
#pragma unroll
    for (int i = 0; i < 4; i++) {
        v[i] = xr[threadIdx.x + i * 256];
        s += v[i];
        s2 += v[i] * v[i];
    }
    int lane = threadIdx.x & 31, warp = threadIdx.x >> 5;
#pragma unroll
    for (int off = 16; off > 0; off >>= 1) {
        s  += __shfl_xor_sync(0xffffffffu, s,  off);
        s2 += __shfl_xor_sync(0xffffffffu, s2, off);
    }
    __shared__ float sm[8], sm2[8];
    if (lane == 0) { sm[warp] = s; sm2[warp] = s2; }
    __syncthreads();
    if (threadIdx.x == 0) {
        float a = 0.f, b = 0.f;
#pragma unroll
        for (int i = 0; i < 8; i++) { a += sm[i]; b += sm2[i]; }
        float mean = a * (1.0f / DD);
        float var  = b * (1.0f / DD) - mean * mean;
        sm[0] = mean;
        sm2[0] = rsqrtf(var + 1e-5f);
    }
    __syncthreads();
    float mean = sm[0], inv = sm2[0];
    float* orow = out + (long)row * DD;
#pragma unroll
    for (int i = 0; i < 4; i++) {
        int c = threadIdx.x + i * 256;
        orow[c] = tf32rf((v[i] - mean) * inv * g[c] + bt[c]);
    }
}

// ---------------- Sparse attention (outputs tf32-rounded) ----------------
__global__ __launch_bounds__(256) void attn_kernel(const float* __restrict__ qkv,
                                                   const int* __restrict__ am,
                                                   float* __restrict__ o)
{
    __shared__ float sc[8][160];
    int warp = threadIdx.x >> 5, lane = threadIdx.x & 31;
    long gw = (long)blockIdx.x * 8 + warp;
    int s = (int)(gw % SS);
    int h = (int)((gw / SS) % HH);
    int b = (int)(gw / ((long)SS * HH));

    const float* qp = qkv + ((long)(b * SS + s)) * (3 * DD) + h * DH + lane * 2;
    float2 q = *(const float2*)qp;

    int gend = min(s + 1, NGLOB);
    int wstart = max(NGLOB, s - WINDOW);
    int nwin = (s >= NGLOB) ? (s - wstart + 1) : 0;
    int nk = gend + nwin;

    float mx = -1e30f;
    for (int idx = 0; idx < nk; idx++) {
        int j = (idx < gend) ? idx : (wstart + (idx - gend));
        const float* kp = qkv + ((long)(b * SS + j)) * (3 * DD) + DD + h * DH + lane * 2;
        float2 k2 = *(const float2*)kp;
        float p = q.x * k2.x + q.y * k2.y;
        p += __shfl_xor_sync(0xffffffffu, p, 16);
        p += __shfl_xor_sync(0xffffffffu, p, 8);
        p += __shfl_xor_sync(0xffffffffu, p, 4);
        p += __shfl_xor_sync(0xffffffffu, p, 2);
        p += __shfl_xor_sync(0xffffffffu, p, 1);
        p *= 0.125f;
        if (am[b * SS + j] == 0) p = NEGV;
        if (lane == 0) sc[warp][idx] = p;
        mx = fmaxf(mx, p);
    }
    __syncwarp();

    float denom = 0.f;
    float2 acc = make_float2(0.f, 0.f);
    for (int idx = 0; idx < nk; idx++) {
        int j = (idx < gend) ? idx : (wstart + (idx - gend));
        float pv = __expf(sc[warp][idx] - mx);
        const float* vp = qkv + ((long)(b * SS + j)) * (3 * DD) + 2 * DD + h * DH + lane * 2;
        float2 v2 = *(const float2*)vp;
        acc.x = fmaf(pv, v2.x, acc.x);
        acc.y = fmaf(pv, v2.y, acc.y);
        denom += pv;
    }
    float inv = 1.f / denom;
    float* op = o + ((long)(b * SS + s)) * DD + h * DH + lane * 2;
    op[0] = tf32rf(acc.x * inv);
    op[1] = tf32rf(acc.y * inv);
}

// ---------------- launch ----------------
extern "C" void kernel_launch(void* const* d_in, const int* in_sizes, int n_in,
                              void* d_out, int out_size)
{
    const float* x     = (const float*)d_in[0];
    const int*   am    = (const int*)  d_in[1];
    const float* w_in  = (const float*)d_in[2];
    const float* b_in  = (const float*)d_in[3];
    const float* w_out = (const float*)d_in[4];
    const float* b_out = (const float*)d_in[5];
    const float* g1    = (const float*)d_in[6];
    const float* bl1   = (const float*)d_in[7];
    const float* g2    = (const float*)d_in[8];
    const float* bl2   = (const float*)d_in[9];
    const float* w1    = (const float*)d_in[10];
    const float* b1    = (const float*)d_in[11];
    const float* w2    = (const float*)d_in[12];
    const float* b2    = (const float*)d_in[13];
    float* out = (float*)d_out;

    void *p_hln, *p_qkv, *p_o, *p_x1, *p_h2, *p_wr;
    cudaGetSymbolAddress(&p_hln, g_hln);
    cudaGetSymbolAddress(&p_qkv, g_qkv);
    cudaGetSymbolAddress(&p_o,   g_o);
    cudaGetSymbolAddress(&p_x1,  g_x1);
    cudaGetSymbolAddress(&p_h2,  g_h2);
    cudaGetSymbolAddress(&p_wr,  g_wr);
    float* hln = (float*)p_hln;
    float* qkv = (float*)p_qkv;
    float* o   = (float*)p_o;
    float* x1  = (float*)p_x1;
    float* h2  = (float*)p_h2;
    float* wr  = (float*)p_wr;

    cudaFuncSetAttribute(gemm_mma<false, false, false>, cudaFuncAttributeMaxDynamicSharedMemorySize, GEMM_SMEM);
    cudaFuncSetAttribute(gemm_mma<false, true,  false>, cudaFuncAttributeMaxDynamicSharedMemorySize, GEMM_SMEM);
    cudaFuncSetAttribute(gemm_mma<true,  false, true >, cudaFuncAttributeMaxDynamicSharedMemorySize, GEMM_SMEM);

    // 0. round weights to tf32
    wprep_kernel<<<WTOTAL / (256 * 4), 256>>>(w_in, w_out, w1, w2);
    // 1. LN1
    ln_kernel<<<ROWS, 256>>>(x, g1, bl1, hln);
    // 2. qkv = hln @ w_in^T + b_in
    gemm_mma<false, false, false><<<dim3(3 * DD / 128, ROWS / 128), 256, GEMM_SMEM>>>(hln, wr + OFF_WIN, b_in, nullptr, qkv, ROWS, 3 * DD, DD);
    // 3. attention -> o
    attn_kernel<<<(BB * HH * SS) / 8, 256>>>(qkv, am, o);
    // 4. x1 = x + o @ w_out^T + b_out
    gemm_mma<false, true, false><<<dim3(DD / 128, ROWS / 128), 256, GEMM_SMEM>>>(o, wr + OFF_WOUT, b_out, x, x1, ROWS, DD, DD);
    // 5. LN2
    ln_kernel<<<ROWS, 256>>>(x1, g2, bl2, hln);
    // 6. h2 = gelu(hln @ w1^T + b1), tf32-rounded
    gemm_mma<true, false, true><<<dim3(FF / 128, ROWS / 128), 256, GEMM_SMEM>>>(hln, wr + OFF_W1, b1, nullptr, h2, ROWS, FF, DD);
    // 7. out = x1 + h2 @ w2^T + b2
    gemm_mma<false, true, false><<<dim3(DD / 128, ROWS / 128), 256, GEMM_SMEM>>>(h2, wr + OFF_W2, b2, x1, out, ROWS, DD, FF);
}

// round 5
// speedup vs baseline: 3.6413x; 1.4608x over previous
#include <cuda_runtime.h>
#include <math.h>
#include <cstdint>

// Problem constants
#define BB 2
#define SS 2048
#define DD 1024
#define HH 16
#define DH 64
#define FF 4096
#define ROWS (BB*SS)          // 4096
#define WINDOW 128
#define NGLOB 16
#define NEGV -1e9f

// weight offsets inside g_wr
#define OFF_WIN  0
#define OFF_WOUT (3*DD*DD)
#define OFF_W1   (OFF_WOUT + DD*DD)
#define OFF_W2   (OFF_W1 + FF*DD)
#define WTOTAL   (OFF_W2 + DD*FF)

// ---------------- scratch ----------------
__device__ float g_hln[ROWS * DD];
__device__ float g_qkv[ROWS * 3 * DD];
__device__ float g_o  [ROWS * DD];
__device__ float g_x1 [ROWS * DD];
__device__ float g_h2 [ROWS * FF];
__device__ float g_wr [WTOTAL];

// ---------------- helpers ----------------
__device__ __forceinline__ float tf32rf(float f) {
    uint32_t u;
    asm("cvt.rna.tf32.f32 %0, %1;" : "=r"(u) : "f"(f));
    return __uint_as_float(u);
}
__device__ __forceinline__ uint32_t smem_u32(const void* p) {
    uint32_t a;
    asm("{ .reg .u64 t; cvta.to.shared.u64 t, %1; cvt.u32.u64 %0, t; }" : "=r"(a) : "l"(p));
    return a;
}
#define CP_ASYNC16(sdst, gsrc) \
    asm volatile("cp.async.cg.shared.global [%0], [%1], 16;" :: "r"(sdst), "l"(gsrc))
#define CP_COMMIT() asm volatile("cp.async.commit_group;" ::: "memory")
#define CP_WAIT2()  asm volatile("cp.async.wait_group 2;" ::: "memory")

#define LDSM_X4(r0, r1, r2, r3, addr) \
    asm volatile("ldmatrix.sync.aligned.m8n8.x4.shared.b16 {%0,%1,%2,%3}, [%4];" \
        : "=r"(r0), "=r"(r1), "=r"(r2), "=r"(r3) : "r"(addr))

#define MMA_TF32(c, a, b) \
    asm volatile("mma.sync.aligned.m16n8k8.row.col.f32.tf32.tf32.f32 " \
        "{%0,%1,%2,%3}, {%4,%5,%6,%7}, {%8,%9}, {%0,%1,%2,%3};" \
        : "+f"((c)[0]), "+f"((c)[1]), "+f"((c)[2]), "+f"((c)[3]) \
        : "r"((a)[0]), "r"((a)[1]), "r"((a)[2]), "r"((a)[3]), \
          "r"((b)[0]), "r"((b)[1]))

// ---------------- weight tf32 pre-round ----------------
__global__ __launch_bounds__(256) void wprep_kernel(const float* __restrict__ w_in,
                                                    const float* __restrict__ w_out,
                                                    const float* __restrict__ w1,
                                                    const float* __restrict__ w2)
{
    long i = ((long)blockIdx.x * 256 + threadIdx.x) * 4;
    float4 v;
    if (i < OFF_WOUT)      v = *(const float4*)(w_in + i);
    else if (i < OFF_W1)   v = *(const float4*)(w_out + (i - OFF_WOUT));
    else if (i < OFF_W2)   v = *(const float4*)(w1 + (i - OFF_W1));
    else                   v = *(const float4*)(w2 + (i - OFF_W2));
    v.x = tf32rf(v.x); v.y = tf32rf(v.y); v.z = tf32rf(v.z); v.w = tf32rf(v.w);
    *(float4*)(g_wr + i) = v;
}

// ---------------- tf32 mma.sync GEMM (cp.async 4-stage, ldmatrix fragments) ----------------
#define ASTRIDE_B 80
#define STAGE_BYTES 10240
#define NSTAGES 4
#define GEMM_SMEM (2 * NSTAGES * STAGE_BYTES)

template <bool GELU, bool RES, bool RTF>
__global__ __launch_bounds__(256, 2) void gemm_mma(const float* __restrict__ A,
                                                   const float* __restrict__ W,
                                                   const float* __restrict__ bias,
                                                   const float* __restrict__ res,
                                                   float* __restrict__ C,
                                                   int M, int N, int K)
{
    extern __shared__ char smem[];
    uint32_t sA = smem_u32(smem);
    uint32_t sB = sA + NSTAGES * STAGE_BYTES;

    int tid = threadIdx.x;
    int lane = tid & 31, wid = tid >> 5;
    int m0 = blockIdx.y * 128;
    int n0 = blockIdx.x * 128;
    int wm = (wid & 1) * 64;
    int wn = (wid >> 1) * 32;

    int ldr0 = tid >> 2;
    int ldr1 = ldr0 + 64;
    int ldc  = (tid & 3) * 16;
    const float* Ag0 = A + (long)(m0 + ldr0) * K + (tid & 3) * 4;
    const float* Ag1 = A + (long)(m0 + ldr1) * K + (tid & 3) * 4;
    const float* Bg0 = W + (long)(n0 + ldr0) * K + (tid & 3) * 4;
    const float* Bg1 = W + (long)(n0 + ldr1) * K + (tid & 3) * 4;
    uint32_t sa0 = sA + ldr0 * ASTRIDE_B + ldc;
    uint32_t sa1 = sA + ldr1 * ASTRIDE_B + ldc;
    uint32_t sb0 = sB + ldr0 * ASTRIDE_B + ldc;
    uint32_t sb1 = sB + ldr1 * ASTRIDE_B + ldc;

    int g = lane >> 3;
    int rl = lane & 7;
    uint32_t aoff = (uint32_t)(((g & 1) * 8 + rl) * ASTRIDE_B + (g >> 1) * 16) + (wm * ASTRIDE_B);
    uint32_t boff = (uint32_t)(((g >> 1) * 8 + rl) * ASTRIDE_B + (g & 1) * 16) + (wn * ASTRIDE_B);

    float acc[4][4][4];
#pragma unroll
    for (int i = 0; i < 4; i++)
#pragma unroll
        for (int j = 0; j < 4; j++)
#pragma unroll
            for (int c = 0; c < 4; c++) acc[i][j][c] = 0.f;

    int nIter = K >> 4;
#pragma unroll
    for (int s = 0; s < NSTAGES - 1; s++) {
        long k0 = (long)s << 4;
        uint32_t so = s * STAGE_BYTES;
        CP_ASYNC16(sa0 + so, Ag0 + k0);
        CP_ASYNC16(sa1 + so, Ag1 + k0);
        CP_ASYNC16(sb0 + so, Bg0 + k0);
        CP_ASYNC16(sb1 + so, Bg1 + k0);
        CP_COMMIT();
    }

    for (int it = 0; it < nIter; it++) {
        CP_WAIT2();
        __syncthreads();
        if (it + NSTAGES - 1 < nIter) {
            long k0 = (long)(it + NSTAGES - 1) << 4;
            uint32_t so = ((it + NSTAGES - 1) & (NSTAGES - 1)) * STAGE_BYTES;
            CP_ASYNC16(sa0 + so, Ag0 + k0);
            CP_ASYNC16(sa1 + so, Ag1 + k0);
            CP_ASYNC16(sb0 + so, Bg0 + k0);
            CP_ASYNC16(sb1 + so, Bg1 + k0);
        }
        CP_COMMIT();

        uint32_t slot = (it & (NSTAGES - 1)) * STAGE_BYTES;
        uint32_t abase = sA + slot + aoff;
        uint32_t bbase = sB + slot + boff;
#pragma unroll
        for (int ks = 0; ks < 2; ks++) {
            uint32_t af[4][4], bf[4][2];
#pragma unroll
            for (int mi = 0; mi < 4; mi++)
                LDSM_X4(af[mi][0], af[mi][1], af[mi][2], af[mi][3],
                        abase + mi * (16 * ASTRIDE_B) + ks * 32);
#pragma unroll
            for (int p = 0; p < 2; p++)
                LDSM_X4(bf[2*p][0], bf[2*p][1], bf[2*p+1][0], bf[2*p+1][1],
                        bbase + p * (16 * ASTRIDE_B) + ks * 32);
#pragma unroll
            for (int mi = 0; mi < 4; mi++)
#pragma unroll
                for (int ni = 0; ni < 4; ni++)
                    MMA_TF32(acc[mi][ni], af[mi], bf[ni]);
        }
        __syncthreads();
    }

#pragma unroll
    for (int mi = 0; mi < 4; mi++) {
        long r_lo = m0 + wm + mi * 16 + (lane >> 2);
        long r_hi = r_lo + 8;
#pragma unroll
        for (int ni = 0; ni < 4; ni++) {
            int col = n0 + wn + ni * 8 + (lane & 3) * 2;
            float2 bv = *(const float2*)(bias + col);
            float v0 = acc[mi][ni][0] + bv.x;
            float v1 = acc[mi][ni][1] + bv.y;
            float v2 = acc[mi][ni][2] + bv.x;
            float v3 = acc[mi][ni][3] + bv.y;
            if (RES) {
                float2 r0 = *(const float2*)(res + r_lo * N + col);
                float2 r1 = *(const float2*)(res + r_hi * N + col);
                v0 += r0.x; v1 += r0.y; v2 += r1.x; v3 += r1.y;
            }
            if (GELU) {
                v0 = 0.5f * v0 * (1.0f + erff(v0 * 0.70710678118654752f));
                v1 = 0.5f * v1 * (1.0f + erff(v1 * 0.70710678118654752f));
                v2 = 0.5f * v2 * (1.0f + erff(v2 * 0.70710678118654752f));
                v3 = 0.5f * v3 * (1.0f + erff(v3 * 0.70710678118654752f));
            }
            if (RTF) {
                v0 = tf32rf(v0); v1 = tf32rf(v1); v2 = tf32rf(v2); v3 = tf32rf(v3);
            }
            *(float2*)(C + r_lo * N + col) = make_float2(v0, v1);
            *(float2*)(C + r_hi * N + col) = make_float2(v2, v3);
        }
    }
}

// ---------------- LayerNorm (outputs tf32-rounded) ----------------
__global__ __launch_bounds__(256) void ln_kernel(const float* __restrict__ x,
                                                 const float* __restrict__ g,
                                                 const float* __restrict__ bt,
                                                 float* __restrict__ out)
{
    int row = blockIdx.x;
    const float* xr = x + (long)row * DD;
    float v[4];
    float s = 0.f, s2 = 0.f;
#pragma unroll
    for (int i = 0; i < 4; i++) {
        v[i] = xr[threadIdx.x + i * 256];
        s += v[i];
        s2 += v[i] * v[i];
    }
    int lane = threadIdx.x & 31, warp = threadIdx.x >> 5;
#pragma unroll
    for (int off = 16; off > 0; off >>= 1) {
        s  += __shfl_xor_sync(0xffffffffu, s,  off);
        s2 += __shfl_xor_sync(0xffffffffu, s2, off);
    }
    __shared__ float sm[8], sm2[8];
    if (lane == 0) { sm[warp] = s; sm2[warp] = s2; }
    __syncthreads();
    if (threadIdx.x == 0) {
        float a = 0.f, b = 0.f;
#pragma unroll
        for (int i = 0; i < 8; i++) { a += sm[i]; b += sm2[i]; }
        float mean = a * (1.0f / DD);
        float var  = b * (1.0f / DD) - mean * mean;
        sm[0] = mean;
        sm2[0] = rsqrtf(var + 1e-5f);
    }
    __syncthreads();
    float mean = sm[0], inv = sm2[0];
    float* orow = out + (long)row * DD;
#pragma unroll
    for (int i = 0; i < 4; i++) {
        int c = threadIdx.x + i * 256;
        orow[c] = tf32rf((v[i] - mean) * inv * g[c] + bt[c]);
    }
}

// ---------------- mma-tiled sparse attention ----------------
// One CTA per (b, h, 64-query tile). Keys padded to 256 (<=208 real).
// smem (floats): sQ 64x68 | sKV 256x72 (K@stride68, V@stride72) | sS 64x260 | sAm 256 | sDen 64
#define QT 64
#define KP 256
#define QSTR 68
#define KSTR 68
#define VSTR 72
#define SSTR 260
#define ATTN_SMEM ((QT*QSTR + KP*VSTR + QT*SSTR + KP + QT) * 4)

__global__ __launch_bounds__(256, 1) void attn_mma(const float* __restrict__ qkv,
                                                   const int* __restrict__ am,
                                                   float* __restrict__ o)
{
    extern __shared__ float sf[];
    float* sQ  = sf;
    float* sKV = sQ + QT * QSTR;
    float* sS  = sKV + KP * VSTR;
    float* sAm = sS + QT * SSTR;
    float* sDen = sAm + KP;

    uint32_t sQb  = smem_u32(sQ);
    uint32_t sKVb = smem_u32(sKV);
    uint32_t sSb  = smem_u32(sS);

    int tid = threadIdx.x;
    int lane = tid & 31, wid = tid >> 5;
    int q0 = blockIdx.x * QT;
    int h = blockIdx.y & 15;
    int b = blockIdx.y >> 4;

    int koff = max(0, q0 - 128 - NGLOB);
    int NK = min(KP - 48, q0 + QT);      // min(208, q0+64)

    const float* qbase = qkv + ((long)b * SS) * (3 * DD) + h * DH;

    // ---- load Q (tf32-rounded) ----
#pragma unroll
    for (int t = 0; t < 4; t++) {
        int f = tid + t * 256;
        int row = f >> 4, ch = f & 15;
        float4 v = *(const float4*)(qbase + (long)(q0 + row) * (3 * DD) + ch * 4);
        v.x = tf32rf(v.x); v.y = tf32rf(v.y); v.z = tf32rf(v.z); v.w = tf32rf(v.w);
        *(float4*)(sQ + row * QSTR + ch * 4) = v;
    }
    // ---- load K (tf32-rounded, zero-pad) ----
#pragma unroll
    for (int t = 0; t < 16; t++) {
        int f = tid + t * 256;
        int idx = f >> 4, ch = f & 15;
        float4 v = make_float4(0.f, 0.f, 0.f, 0.f);
        if (idx < NK) {
            int key = idx + (idx < NGLOB ? 0 : koff);
            v = *(const float4*)(qbase + (long)key * (3 * DD) + DD + ch * 4);
            v.x = tf32rf(v.x); v.y = tf32rf(v.y); v.z = tf32rf(v.z); v.w = tf32rf(v.w);
        }
        *(float4*)(sKV + idx * KSTR + ch * 4) = v;
    }
    // ---- key-padding mask additive term ----
    if (tid < KP) {
        int idx = tid;
        float a = NEGV;
        if (idx < NK) {
            int key = idx + (idx < NGLOB ? 0 : koff);
            a = (am[b * SS + key] == 0) ? NEGV : 0.f;
        }
        sAm[idx] = a;
    }
    __syncthreads();

    // ---- phase 1: S = Q @ K^T  (warps 2M x 4N; warp tile 32q x 64k) ----
    int g = lane >> 3;
    int rl = lane & 7;
    int wm = (wid & 1) * 32;
    int wn = (wid >> 1) * 64;
    {
        float acc[2][8][4];
#pragma unroll
        for (int i = 0; i < 2; i++)
#pragma unroll
            for (int j = 0; j < 8; j++)
#pragma unroll
                for (int c = 0; c < 4; c++) acc[i][j][c] = 0.f;

        uint32_t aQ = sQb + (wm + (g & 1) * 8 + rl) * (QSTR * 4) + (g >> 1) * 16;
        uint32_t bK = sKVb + (wn + (g >> 1) * 8 + rl) * (KSTR * 4) + (g & 1) * 16;
#pragma unroll
        for (int ks = 0; ks < 8; ks++) {
            uint32_t af[2][4], bf[8][2];
#pragma unroll
            for (int mt = 0; mt < 2; mt++)
                LDSM_X4(af[mt][0], af[mt][1], af[mt][2], af[mt][3],
                        aQ + mt * (16 * QSTR * 4) + ks * 32);
#pragma unroll
            for (int p = 0; p < 4; p++)
                LDSM_X4(bf[2*p][0], bf[2*p][1], bf[2*p+1][0], bf[2*p+1][1],
                        bK + p * (16 * KSTR * 4) + ks * 32);
#pragma unroll
            for (int mt = 0; mt < 2; mt++)
#pragma unroll
                for (int nt = 0; nt < 8; nt++)
                    MMA_TF32(acc[mt][nt], af[mt], bf[nt]);
        }

        // masked scaled store to sS
#pragma unroll
        for (int mt = 0; mt < 2; mt++) {
            int r0 = wm + mt * 16 + (lane >> 2);
            int r1 = r0 + 8;
            int qa0 = q0 + r0, qa1 = q0 + r1;
#pragma unroll
            for (int nt = 0; nt < 8; nt++) {
                int col = wn + nt * 8 + 2 * (lane & 3);
#pragma unroll
                for (int cc = 0; cc < 2; cc++) {
                    int cidx = col + cc;
                    int key = cidx + (cidx < NGLOB ? 0 : koff);
                    float amv = sAm[cidx];
                    bool ok0 = (cidx < NK) && (key <= qa0) && ((key < NGLOB) || (key >= qa0 - WINDOW));
                    bool ok1 = (cidx < NK) && (key <= qa1) && ((key < NGLOB) || (key >= qa1 - WINDOW));
                    sS[r0 * SSTR + cidx] = ok0 ? acc[mt][nt][cc] * 0.125f + amv : NEGV;
                    sS[r1 * SSTR + cidx] = ok1 ? acc[mt][nt][2 + cc] * 0.125f + amv : NEGV;
                }
            }
        }
    }
    __syncthreads();

    // ---- load V (overwrites K region; stride VSTR) ----
#pragma unroll
    for (int t = 0; t < 16; t++) {
        int f = tid + t * 256;
        int idx = f >> 4, ch = f & 15;
        float4 v = make_float4(0.f, 0.f, 0.f, 0.f);
        if (idx < NK) {
            int key = idx + (idx < NGLOB ? 0 : koff);
            v = *(const float4*)(qbase + (long)key * (3 * DD) + 2 * DD + ch * 4);
            v.x = tf32rf(v.x); v.y = tf32rf(v.y); v.z = tf32rf(v.z); v.w = tf32rf(v.w);
        }
        *(float4*)(sKV + idx * VSTR + ch * 4) = v;
    }

    // ---- phase 2: softmax rows (warp w: rows w*8 .. w*8+7) ----
#pragma unroll
    for (int i = 0; i < 8; i++) {
        int r = wid * 8 + i;
        float v[8];
#pragma unroll
        for (int j = 0; j < 8; j++) v[j] = sS[r * SSTR + lane + j * 32];
        float mx = v[0];
#pragma unroll
        for (int j = 1; j < 8; j++) mx = fmaxf(mx, v[j]);
#pragma unroll
        for (int off = 16; off > 0; off >>= 1) mx = fmaxf(mx, __shfl_xor_sync(0xffffffffu, mx, off));
        float sum = 0.f;
#pragma unroll
        for (int j = 0; j < 8; j++) {
            float e = __expf(v[j] - mx);
            e = tf32rf(e);
            sum += e;
            sS[r * SSTR + lane + j * 32] = e;
        }
#pragma unroll
        for (int off = 16; off > 0; off >>= 1) sum += __shfl_xor_sync(0xffffffffu, sum, off);
        if (lane == 0) sDen[r] = sum;
    }
    __syncthreads();

    // ---- phase 3: O = P @ V  (warps 4M x 2N; warp tile 16q x 32d) ----
    {
        int wm2 = (wid & 3) * 16;
        int wn2 = (wid >> 2) * 32;
        float acc2[4][4];
#pragma unroll
        for (int j = 0; j < 4; j++)
#pragma unroll
            for (int c = 0; c < 4; c++) acc2[j][c] = 0.f;

        uint32_t aS = sSb + (wm2 + (g & 1) * 8 + rl) * (SSTR * 4) + (g >> 1) * 16;
#pragma unroll
        for (int ks = 0; ks < 32; ks++) {
            uint32_t af[4];
            LDSM_X4(af[0], af[1], af[2], af[3], aS + ks * 32);
            int k0 = ks * 8 + (lane & 3);
            int nb = wn2 + (lane >> 2);
            uint32_t bf[4][2];
#pragma unroll
            for (int nt = 0; nt < 4; nt++) {
                bf[nt][0] = __float_as_uint(sKV[k0 * VSTR + nb + nt * 8]);
                bf[nt][1] = __float_as_uint(sKV[(k0 + 4) * VSTR + nb + nt * 8]);
            }
#pragma unroll
            for (int nt = 0; nt < 4; nt++)
                MMA_TF32(acc2[nt], af, bf[nt]);
        }

        // normalized, tf32-rounded output
        int r0 = wm2 + (lane >> 2);
        int r1 = r0 + 8;
        float inv0 = 1.f / sDen[r0];
        float inv1 = 1.f / sDen[r1];
        float* ob0 = o + ((long)(b * SS + q0 + r0)) * DD + h * DH;
        float* ob1 = o + ((long)(b * SS + q0 + r1)) * DD + h * DH;
#pragma unroll
        for (int nt = 0; nt < 4; nt++) {
            int col = wn2 + nt * 8 + 2 * (lane & 3);
            *(float2*)(ob0 + col) = make_float2(tf32rf(acc2[nt][0] * inv0), tf32rf(acc2[nt][1] * inv0));
            *(float2*)(ob1 + col) = make_float2(tf32rf(acc2[nt][2] * inv1), tf32rf(acc2[nt][3] * inv1));
        }
    }
}

// ---------------- launch ----------------
extern "C" void kernel_launch(void* const* d_in, const int* in_sizes, int n_in,
                              void* d_out, int out_size)
{
    const float* x     = (const float*)d_in[0];
    const int*   am    = (const int*)  d_in[1];
    const float* w_in  = (const float*)d_in[2];
    const float* b_in  = (const float*)d_in[3];
    const float* w_out = (const float*)d_in[4];
    const float* b_out = (const float*)d_in[5];
    const float* g1    = (const float*)d_in[6];
    const float* bl1   = (const float*)d_in[7];
    const float* g2    = (const float*)d_in[8];
    const float* bl2   = (const float*)d_in[9];
    const float* w1    = (const float*)d_in[10];
    const float* b1    = (const float*)d_in[11];
    const float* w2    = (const float*)d_in[12];
    const float* b2    = (const float*)d_in[13];
    float* out = (float*)d_out;

    void *p_hln, *p_qkv, *p_o, *p_x1, *p_h2, *p_wr;
    cudaGetSymbolAddress(&p_hln, g_hln);
    cudaGetSymbolAddress(&p_qkv, g_qkv);
    cudaGetSymbolAddress(&p_o,   g_o);
    cudaGetSymbolAddress(&p_x1,  g_x1);
    cudaGetSymbolAddress(&p_h2,  g_h2);
    cudaGetSymbolAddress(&p_wr,  g_wr);
    float* hln = (float*)p_hln;
    float* qkv = (float*)p_qkv;
    float* o   = (float*)p_o;
    float* x1  = (float*)p_x1;
    float* h2  = (float*)p_h2;
    float* wr  = (float*)p_wr;

    cudaFuncSetAttribute(gemm_mma<false, false, false>, cudaFuncAttributeMaxDynamicSharedMemorySize, GEMM_SMEM);
    cudaFuncSetAttribute(gemm_mma<false, true,  false>, cudaFuncAttributeMaxDynamicSharedMemorySize, GEMM_SMEM);
    cudaFuncSetAttribute(gemm_mma<true,  false, true >, cudaFuncAttributeMaxDynamicSharedMemorySize, GEMM_SMEM);
    cudaFuncSetAttribute(attn_mma, cudaFuncAttributeMaxDynamicSharedMemorySize, ATTN_SMEM);

    // 0. round weights to tf32
    wprep_kernel<<<WTOTAL / (256 * 4), 256>>>(w_in, w_out, w1, w2);
    // 1. LN1
    ln_kernel<<<ROWS, 256>>>(x, g1, bl1, hln);
    // 2. qkv = hln @ w_in^T + b_in
    gemm_mma<false, false, false><<<dim3(3 * DD / 128, ROWS / 128), 256, GEMM_SMEM>>>(hln, wr + OFF_WIN, b_in, nullptr, qkv, ROWS, 3 * DD, DD);
    // 3. attention -> o
    attn_mma<<<dim3(SS / QT, BB * HH), 256, ATTN_SMEM>>>(qkv, am, o);
    // 4. x1 = x + o @ w_out^T + b_out
    gemm_mma<false, true, false><<<dim3(DD / 128, ROWS / 128), 256, GEMM_SMEM>>>(o, wr + OFF_WOUT, b_out, x, x1, ROWS, DD, DD);
    // 5. LN2
    ln_kernel<<<ROWS, 256>>>(x1, g2, bl2, hln);
    // 6. h2 = gelu(hln @ w1^T + b1), tf32-rounded
    gemm_mma<true, false, true><<<dim3(FF / 128, ROWS / 128), 256, GEMM_SMEM>>>(hln, wr + OFF_W1, b1, nullptr, h2, ROWS, FF, DD);
    // 7. out = x1 + h2 @ w2^T + b2
    gemm_mma<false, true, false><<<dim3(DD / 128, ROWS / 128), 256, GEMM_SMEM>>>(h2, wr + OFF_W2, b2, x1, out, ROWS, DD, FF);
}

// round 6
// speedup vs baseline: 3.6753x; 1.0093x over previous
#include <cuda_runtime.h>
#include <math.h>
#include <cstdint>

// Problem constants
#define BB 2
#define SS 2048
#define DD 1024
#define HH 16
#define DH 64
#define FF 4096
#define ROWS (BB*SS)          // 4096
#define WINDOW 128
#define NGLOB 16
#define NEGV -1e9f

// weight offsets inside g_wr
#define OFF_WIN  0
#define OFF_WOUT (3*DD*DD)
#define OFF_W1   (OFF_WOUT + DD*DD)
#define OFF_W2   (OFF_W1 + FF*DD)
#define WTOTAL   (OFF_W2 + DD*FF)

// ---------------- scratch ----------------
__device__ float g_hln[ROWS * DD];
__device__ float g_qkv[ROWS * 3 * DD];
__device__ float g_o  [ROWS * DD];
__device__ float g_x1 [ROWS * DD];
__device__ float g_h2 [ROWS * FF];
__device__ float g_wr [WTOTAL];

// ---------------- helpers ----------------
__device__ __forceinline__ float tf32rf(float f) {
    uint32_t u;
    asm("cvt.rna.tf32.f32 %0, %1;" : "=r"(u) : "f"(f));
    return __uint_as_float(u);
}
__device__ __forceinline__ uint32_t smem_u32(const void* p) {
    uint32_t a;
    asm("{ .reg .u64 t; cvta.to.shared.u64 t, %1; cvt.u32.u64 %0, t; }" : "=r"(a) : "l"(p));
    return a;
}
#define CP_ASYNC16(sdst, gsrc) \
    asm volatile("cp.async.cg.shared.global [%0], [%1], 16;" :: "r"(sdst), "l"(gsrc))
#define CP_COMMIT() asm volatile("cp.async.commit_group;" ::: "memory")
#define CP_WAIT1()  asm volatile("cp.async.wait_group 1;" ::: "memory")

#define LDSM_X4(r0, r1, r2, r3, addr) \
    asm volatile("ldmatrix.sync.aligned.m8n8.x4.shared.b16 {%0,%1,%2,%3}, [%4];" \
        : "=r"(r0), "=r"(r1), "=r"(r2), "=r"(r3) : "r"(addr))

#define MMA_TF32(c, a, b) \
    asm volatile("mma.sync.aligned.m16n8k8.row.col.f32.tf32.tf32.f32 " \
        "{%0,%1,%2,%3}, {%4,%5,%6,%7}, {%8,%9}, {%0,%1,%2,%3};" \
        : "+f"((c)[0]), "+f"((c)[1]), "+f"((c)[2]), "+f"((c)[3]) \
        : "r"((a)[0]), "r"((a)[1]), "r"((a)[2]), "r"((a)[3]), \
          "r"((b)[0]), "r"((b)[1]))

// ---------------- weight tf32 pre-round ----------------
__global__ __launch_bounds__(256) void wprep_kernel(const float* __restrict__ w_in,
                                                    const float* __restrict__ w_out,
                                                    const float* __restrict__ w1,
                                                    const float* __restrict__ w2)
{
    long i = ((long)blockIdx.x * 256 + threadIdx.x) * 4;
    float4 v;
    if (i < OFF_WOUT)      v = *(const float4*)(w_in + i);
    else if (i < OFF_W1)   v = *(const float4*)(w_out + (i - OFF_WOUT));
    else if (i < OFF_W2)   v = *(const float4*)(w1 + (i - OFF_W1));
    else                   v = *(const float4*)(w2 + (i - OFF_W2));
    v.x = tf32rf(v.x); v.y = tf32rf(v.y); v.z = tf32rf(v.z); v.w = tf32rf(v.w);
    *(float4*)(g_wr + i) = v;
}

// ---------------- tf32 mma.sync GEMM: BK=32, 3-stage cp.async, 1 sync/iter ----------------
#define RSTR 144                          // smem row stride bytes (36 floats)
#define STAGE_BYTES (128 * RSTR)          // 18432 per matrix per stage
#define NSTAGES 3
#define GEMM_SMEM (2 * NSTAGES * STAGE_BYTES)   // 110592

template <bool GELU, bool RES, bool RTF>
__global__ __launch_bounds__(256, 2) void gemm_mma(const float* __restrict__ A,
                                                   const float* __restrict__ W,
                                                   const float* __restrict__ bias,
                                                   const float* __restrict__ res,
                                                   float* __restrict__ C,
                                                   int M, int N, int K)
{
    extern __shared__ char smem[];
    uint32_t sA = smem_u32(smem);
    uint32_t sB = sA + NSTAGES * STAGE_BYTES;

    int tid = threadIdx.x;
    int lane = tid & 31, wid = tid >> 5;
    int m0 = blockIdx.y * 128;
    int n0 = blockIdx.x * 128;
    int wm = (wid & 1) * 64;
    int wn = (wid >> 1) * 32;

    // cp.async mapping: chunk f = tid + i*256 (i<4): row = f>>3, 16B col = f&7
    int r0 = tid >> 3;                  // 0..31
    int c16 = tid & 7;                  // 0..7
    const float* Agp = A + (long)(m0 + r0) * K + c16 * 4;
    const float* Bgp = W + (long)(n0 + r0) * K + c16 * 4;
    uint32_t sa = sA + r0 * RSTR + c16 * 16;
    uint32_t sb = sB + r0 * RSTR + c16 * 16;

#define ISSUE_STAGE(s) do { \
    long k0g = (long)(s) * 32; \
    uint32_t so = ((s) % NSTAGES) * STAGE_BYTES; \
    _Pragma("unroll") \
    for (int i_ = 0; i_ < 4; i_++) { \
        CP_ASYNC16(sa + so + i_ * (32 * RSTR), Agp + (long)(32 * i_) * K + k0g); \
        CP_ASYNC16(sb + so + i_ * (32 * RSTR), Bgp + (long)(32 * i_) * K + k0g); \
    } \
    CP_COMMIT(); } while (0)

    // ldmatrix per-thread offsets
    int g = lane >> 3;
    int rl = lane & 7;
    uint32_t aoff = (uint32_t)(((g & 1) * 8 + rl + wm) * RSTR + (g >> 1) * 16);
    uint32_t boff = (uint32_t)(((g >> 1) * 8 + rl + wn) * RSTR + (g & 1) * 16);

    float acc[4][4][4];
#pragma unroll
    for (int i = 0; i < 4; i++)
#pragma unroll
        for (int j = 0; j < 4; j++)
#pragma unroll
            for (int c = 0; c < 4; c++) acc[i][j][c] = 0.f;

    int nIter = K >> 5;
    ISSUE_STAGE(0);
    ISSUE_STAGE(1);

    for (int it = 0; it < nIter; it++) {
        CP_WAIT1();
        __syncthreads();
        if (it + 2 < nIter) { ISSUE_STAGE(it + 2); } else { CP_COMMIT(); }

        uint32_t slot = (uint32_t)((it % NSTAGES) * STAGE_BYTES);
        uint32_t abase = sA + slot + aoff;
        uint32_t bbase = sB + slot + boff;
#pragma unroll
        for (int ks = 0; ks < 4; ks++) {
            uint32_t af[4][4], bf[4][2];
#pragma unroll
            for (int mi = 0; mi < 4; mi++)
                LDSM_X4(af[mi][0], af[mi][1], af[mi][2], af[mi][3],
                        abase + mi * (16 * RSTR) + ks * 32);
#pragma unroll
            for (int p = 0; p < 2; p++)
                LDSM_X4(bf[2*p][0], bf[2*p][1], bf[2*p+1][0], bf[2*p+1][1],
                        bbase + p * (16 * RSTR) + ks * 32);
#pragma unroll
            for (int mi = 0; mi < 4; mi++)
#pragma unroll
                for (int ni = 0; ni < 4; ni++)
                    MMA_TF32(acc[mi][ni], af[mi], bf[ni]);
        }
        // no bottom sync: top sync of it+1 protects slot reuse
    }
#undef ISSUE_STAGE

    // epilogue
#pragma unroll
    for (int mi = 0; mi < 4; mi++) {
        long r_lo = m0 + wm + mi * 16 + (lane >> 2);
        long r_hi = r_lo + 8;
#pragma unroll
        for (int ni = 0; ni < 4; ni++) {
            int col = n0 + wn + ni * 8 + (lane & 3) * 2;
            float2 bv = *(const float2*)(bias + col);
            float v0 = acc[mi][ni][0] + bv.x;
            float v1 = acc[mi][ni][1] + bv.y;
            float v2 = acc[mi][ni][2] + bv.x;
            float v3 = acc[mi][ni][3] + bv.y;
            if (RES) {
                float2 rr0 = *(const float2*)(res + r_lo * N + col);
                float2 rr1 = *(const float2*)(res + r_hi * N + col);
                v0 += rr0.x; v1 += rr0.y; v2 += rr1.x; v3 += rr1.y;
            }
            if (GELU) {
                v0 = 0.5f * v0 * (1.0f + erff(v0 * 0.70710678118654752f));
                v1 = 0.5f * v1 * (1.0f + erff(v1 * 0.70710678118654752f));
                v2 = 0.5f * v2 * (1.0f + erff(v2 * 0.70710678118654752f));
                v3 = 0.5f * v3 * (1.0f + erff(v3 * 0.70710678118654752f));
            }
            if (RTF) {
                v0 = tf32rf(v0); v1 = tf32rf(v1); v2 = tf32rf(v2); v3 = tf32rf(v3);
            }
            *(float2*)(C + r_lo * N + col) = make_float2(v0, v1);
            *(float2*)(C + r_hi * N + col) = make_float2(v2, v3);
        }
    }
}

// ---------------- LayerNorm (outputs tf32-rounded) ----------------
__global__ __launch_bounds__(256) void ln_kernel(const float* __restrict__ x,
                                                 const float* __restrict__ g,
                                                 const float* __restrict__ bt,
                                                 float* __restrict__ out)
{
    int row = blockIdx.x;
    const float* xr = x + (long)row * DD;
    float v[4];
    float s = 0.f, s2 = 0.f;
#pragma unroll
    for (int i = 0; i < 4; i++) {
        v[i] = xr[threadIdx.x + i * 256];
        s += v[i];
        s2 += v[i] * v[i];
    }
    int lane = threadIdx.x & 31, warp = threadIdx.x >> 5;
#pragma unroll
    for (int off = 16; off > 0; off >>= 1) {
        s  += __shfl_xor_sync(0xffffffffu, s,  off);
        s2 += __shfl_xor_sync(0xffffffffu, s2, off);
    }
    __shared__ float sm[8], sm2[8];
    if (lane == 0) { sm[warp] = s; sm2[warp] = s2; }
    __syncthreads();
    if (threadIdx.x == 0) {
        float a = 0.f, b = 0.f;
#pragma unroll
        for (int i = 0; i < 8; i++) { a += sm[i]; b += sm2[i]; }
        float mean = a * (1.0f / DD);
        float var  = b * (1.0f / DD) - mean * mean;
        sm[0] = mean;
        sm2[0] = rsqrtf(var + 1e-5f);
    }
    __syncthreads();
    float mean = sm[0], inv = sm2[0];
    float* orow = out + (long)row * DD;
#pragma unroll
    for (int i = 0; i < 4; i++) {
        int c = threadIdx.x + i * 256;
        orow[c] = tf32rf((v[i] - mean) * inv * g[c] + bt[c]);
    }
}

// ---------------- mma-tiled sparse attention ----------------
#define QT 64
#define KP 256
#define QSTR 68
#define KSTR 68
#define VSTR 72
#define SSTR 260
#define ATTN_SMEM ((QT*QSTR + KP*VSTR + QT*SSTR + KP + QT) * 4)

__global__ __launch_bounds__(256, 1) void attn_mma(const float* __restrict__ qkv,
                                                   const int* __restrict__ am,
                                                   float* __restrict__ o)
{
    extern __shared__ float sf[];
    float* sQ  = sf;
    float* sKV = sQ + QT * QSTR;
    float* sS  = sKV + KP * VSTR;
    float* sAm = sS + QT * SSTR;
    float* sDen = sAm + KP;

    uint32_t sQb  = smem_u32(sQ);
    uint32_t sKVb = smem_u32(sKV);
    uint32_t sSb  = smem_u32(sS);

    int tid = threadIdx.x;
    int lane = tid & 31, wid = tid >> 5;
    int q0 = blockIdx.x * QT;
    int h = blockIdx.y & 15;
    int b = blockIdx.y >> 4;

    int koff = max(0, q0 - 128 - NGLOB);
    int NK = min(KP - 48, q0 + QT);

    const float* qbase = qkv + ((long)b * SS) * (3 * DD) + h * DH;

#pragma unroll
    for (int t = 0; t < 4; t++) {
        int f = tid + t * 256;
        int row = f >> 4, ch = f & 15;
        float4 v = *(const float4*)(qbase + (long)(q0 + row) * (3 * DD) + ch * 4);
        v.x = tf32rf(v.x); v.y = tf32rf(v.y); v.z = tf32rf(v.z); v.w = tf32rf(v.w);
        *(float4*)(sQ + row * QSTR + ch * 4) = v;
    }
#pragma unroll
    for (int t = 0; t < 16; t++) {
        int f = tid + t * 256;
        int idx = f >> 4, ch = f & 15;
        float4 v = make_float4(0.f, 0.f, 0.f, 0.f);
        if (idx < NK) {
            int key = idx + (idx < NGLOB ? 0 : koff);
            v = *(const float4*)(qbase + (long)key * (3 * DD) + DD + ch * 4);
            v.x = tf32rf(v.x); v.y = tf32rf(v.y); v.z = tf32rf(v.z); v.w = tf32rf(v.w);
        }
        *(float4*)(sKV + idx * KSTR + ch * 4) = v;
    }
    if (tid < KP) {
        int idx = tid;
        float a = NEGV;
        if (idx < NK) {
            int key = idx + (idx < NGLOB ? 0 : koff);
            a = (am[b * SS + key] == 0) ? NEGV : 0.f;
        }
        sAm[idx] = a;
    }
    __syncthreads();

    int g = lane >> 3;
    int rl = lane & 7;
    int wm = (wid & 1) * 32;
    int wn = (wid >> 1) * 64;
    {
        float acc[2][8][4];
#pragma unroll
        for (int i = 0; i < 2; i++)
#pragma unroll
            for (int j = 0; j < 8; j++)
#pragma unroll
                for (int c = 0; c < 4; c++) acc[i][j][c] = 0.f;

        uint32_t aQ = sQb + (wm + (g & 1) * 8 + rl) * (QSTR * 4) + (g >> 1) * 16;
        uint32_t bK = sKVb + (wn + (g >> 1) * 8 + rl) * (KSTR * 4) + (g & 1) * 16;
#pragma unroll
        for (int ks = 0; ks < 8; ks++) {
            uint32_t af[2][4], bf[8][2];
#pragma unroll
            for (int mt = 0; mt < 2; mt++)
                LDSM_X4(af[mt][0], af[mt][1], af[mt][2], af[mt][3],
                        aQ + mt * (16 * QSTR * 4) + ks * 32);
#pragma unroll
            for (int p = 0; p < 4; p++)
                LDSM_X4(bf[2*p][0], bf[2*p][1], bf[2*p+1][0], bf[2*p+1][1],
                        bK + p * (16 * KSTR * 4) + ks * 32);
#pragma unroll
            for (int mt = 0; mt < 2; mt++)
#pragma unroll
                for (int nt = 0; nt < 8; nt++)
                    MMA_TF32(acc[mt][nt], af[mt], bf[nt]);
        }

#pragma unroll
        for (int mt = 0; mt < 2; mt++) {
            int r0 = wm + mt * 16 + (lane >> 2);
            int r1 = r0 + 8;
            int qa0 = q0 + r0, qa1 = q0 + r1;
#pragma unroll
            for (int nt = 0; nt < 8; nt++) {
                int col = wn + nt * 8 + 2 * (lane & 3);
#pragma unroll
                for (int cc = 0; cc < 2; cc++) {
                    int cidx = col + cc;
                    int key = cidx + (cidx < NGLOB ? 0 : koff);
                    float amv = sAm[cidx];
                    bool ok0 = (cidx < NK) && (key <= qa0) && ((key < NGLOB) || (key >= qa0 - WINDOW));
                    bool ok1 = (cidx < NK) && (key <= qa1) && ((key < NGLOB) || (key >= qa1 - WINDOW));
                    sS[r0 * SSTR + cidx] = ok0 ? acc[mt][nt][cc] * 0.125f + amv : NEGV;
                    sS[r1 * SSTR + cidx] = ok1 ? acc[mt][nt][2 + cc] * 0.125f + amv : NEGV;
                }
            }
        }
    }
    __syncthreads();

#pragma unroll
    for (int t = 0; t < 16; t++) {
        int f = tid + t * 256;
        int idx = f >> 4, ch = f & 15;
        float4 v = make_float4(0.f, 0.f, 0.f, 0.f);
        if (idx < NK) {
            int key = idx + (idx < NGLOB ? 0 : koff);
            v = *(const float4*)(qbase + (long)key * (3 * DD) + 2 * DD + ch * 4);
            v.x = tf32rf(v.x); v.y = tf32rf(v.y); v.z = tf32rf(v.z); v.w = tf32rf(v.w);
        }
        *(float4*)(sKV + idx * VSTR + ch * 4) = v;
    }

#pragma unroll
    for (int i = 0; i < 8; i++) {
        int r = wid * 8 + i;
        float v[8];
#pragma unroll
        for (int j = 0; j < 8; j++) v[j] = sS[r * SSTR + lane + j * 32];
        float mx = v[0];
#pragma unroll
        for (int j = 1; j < 8; j++) mx = fmaxf(mx, v[j]);
#pragma unroll
        for (int off = 16; off > 0; off >>= 1) mx = fmaxf(mx, __shfl_xor_sync(0xffffffffu, mx, off));
        float sum = 0.f;
#pragma unroll
        for (int j = 0; j < 8; j++) {
            float e = __expf(v[j] - mx);
            e = tf32rf(e);
            sum += e;
            sS[r * SSTR + lane + j * 32] = e;
        }
#pragma unroll
        for (int off = 16; off > 0; off >>= 1) sum += __shfl_xor_sync(0xffffffffu, sum, off);
        if (lane == 0) sDen[r] = sum;
    }
    __syncthreads();

    {
        int wm2 = (wid & 3) * 16;
        int wn2 = (wid >> 2) * 32;
        float acc2[4][4];
#pragma unroll
        for (int j = 0; j < 4; j++)
#pragma unroll
            for (int c = 0; c < 4; c++) acc2[j][c] = 0.f;

        uint32_t aS = sSb + (wm2 + (g & 1) * 8 + rl) * (SSTR * 4) + (g >> 1) * 16;
#pragma unroll
        for (int ks = 0; ks < 32; ks++) {
            uint32_t af[4];
            LDSM_X4(af[0], af[1], af[2], af[3], aS + ks * 32);
            int k0 = ks * 8 + (lane & 3);
            int nb = wn2 + (lane >> 2);
            uint32_t bf[4][2];
#pragma unroll
            for (int nt = 0; nt < 4; nt++) {
                bf[nt][0] = __float_as_uint(sKV[k0 * VSTR + nb + nt * 8]);
                bf[nt][1] = __float_as_uint(sKV[(k0 + 4) * VSTR + nb + nt * 8]);
            }
#pragma unroll
            for (int nt = 0; nt < 4; nt++)
                MMA_TF32(acc2[nt], af, bf[nt]);
        }

        int r0o = wm2 + (lane >> 2);
        int r1o = r0o + 8;
        float inv0 = 1.f / sDen[r0o];
        float inv1 = 1.f / sDen[r1o];
        float* ob0 = o + ((long)(b * SS + q0 + r0o)) * DD + h * DH;
        float* ob1 = o + ((long)(b * SS + q0 + r1o)) * DD + h * DH;
#pragma unroll
        for (int nt = 0; nt < 4; nt++) {
            int col = wn2 + nt * 8 + 2 * (lane & 3);
            *(float2*)(ob0 + col) = make_float2(tf32rf(acc2[nt][0] * inv0), tf32rf(acc2[nt][1] * inv0));
            *(float2*)(ob1 + col) = make_float2(tf32rf(acc2[nt][2] * inv1), tf32rf(acc2[nt][3] * inv1));
        }
    }
}

// ---------------- launch ----------------
extern "C" void kernel_launch(void* const* d_in, const int* in_sizes, int n_in,
                              void* d_out, int out_size)
{
    const float* x     = (const float*)d_in[0];
    const int*   am    = (const int*)  d_in[1];
    const float* w_in  = (const float*)d_in[2];
    const float* b_in  = (const float*)d_in[3];
    const float* w_out = (const float*)d_in[4];
    const float* b_out = (const float*)d_in[5];
    const float* g1    = (const float*)d_in[6];
    const float* bl1   = (const float*)d_in[7];
    const float* g2    = (const float*)d_in[8];
    const float* bl2   = (const float*)d_in[9];
    const float* w1    = (const float*)d_in[10];
    const float* b1    = (const float*)d_in[11];
    const float* w2    = (const float*)d_in[12];
    const float* b2    = (const float*)d_in[13];
    float* out = (float*)d_out;

    void *p_hln, *p_qkv, *p_o, *p_x1, *p_h2, *p_wr;
    cudaGetSymbolAddress(&p_hln, g_hln);
    cudaGetSymbolAddress(&p_qkv, g_qkv);
    cudaGetSymbolAddress(&p_o,   g_o);
    cudaGetSymbolAddress(&p_x1,  g_x1);
    cudaGetSymbolAddress(&p_h2,  g_h2);
    cudaGetSymbolAddress(&p_wr,  g_wr);
    float* hln = (float*)p_hln;
    float* qkv = (float*)p_qkv;
    float* o   = (float*)p_o;
    float* x1  = (float*)p_x1;
    float* h2  = (float*)p_h2;
    float* wr  = (float*)p_wr;

    cudaFuncSetAttribute(gemm_mma<false, false, false>, cudaFuncAttributeMaxDynamicSharedMemorySize, GEMM_SMEM);
    cudaFuncSetAttribute(gemm_mma<false, true,  false>, cudaFuncAttributeMaxDynamicSharedMemorySize, GEMM_SMEM);
    cudaFuncSetAttribute(gemm_mma<true,  false, true >, cudaFuncAttributeMaxDynamicSharedMemorySize, GEMM_SMEM);
    cudaFuncSetAttribute(attn_mma, cudaFuncAttributeMaxDynamicSharedMemorySize, ATTN_SMEM);

    // 0. round weights to tf32
    wprep_kernel<<<WTOTAL / (256 * 4), 256>>>(w_in, w_out, w1, w2);
    // 1. LN1
    ln_kernel<<<ROWS, 256>>>(x, g1, bl1, hln);
    // 2. qkv = hln @ w_in^T + b_in
    gemm_mma<false, false, false><<<dim3(3 * DD / 128, ROWS / 128), 256, GEMM_SMEM>>>(hln, wr + OFF_WIN, b_in, nullptr, qkv, ROWS, 3 * DD, DD);
    // 3. attention -> o
    attn_mma<<<dim3(SS / QT, BB * HH), 256, ATTN_SMEM>>>(qkv, am, o);
    // 4. x1 = x + o @ w_out^T + b_out
    gemm_mma<false, true, false><<<dim3(DD / 128, ROWS / 128), 256, GEMM_SMEM>>>(o, wr + OFF_WOUT, b_out, x, x1, ROWS, DD, DD);
    // 5. LN2
    ln_kernel<<<ROWS, 256>>>(x1, g2, bl2, hln);
    // 6. h2 = gelu(hln @ w1^T + b1), tf32-rounded
    gemm_mma<true, false, true><<<dim3(FF / 128, ROWS / 128), 256, GEMM_SMEM>>>(hln, wr + OFF_W1, b1, nullptr, h2, ROWS, FF, DD);
    // 7. out = x1 + h2 @ w2^T + b2
    gemm_mma<false, true, false><<<dim3(DD / 128, ROWS / 128), 256, GEMM_SMEM>>>(h2, wr + OFF_W2, b2, x1, out, ROWS, DD, FF);
}